// round 11
// baseline (speedup 1.0000x reference)
#include <cuda_runtime.h>
#include <cuda_fp16.h>

#define NMAX 100000
#define EPSF 1e-5f

// q/k/v projection scratch in fp16 (device globals: allocation-free).
// Row = 32 half2 = 64 channels = 128 bytes (one L2/L1 line per row).
__device__ __half2 g_xq[NMAX * 32];
__device__ __half2 g_xk[NMAX * 32];
__device__ __half2 g_xv[NMAX * 32];

__device__ __forceinline__ float4 ldg_h4(const __half2* __restrict__ base,
                                         size_t row, int sub) {
    uint2 u = *(const uint2*)(base + row * 32 + sub * 2);
    __half2 a = *(__half2*)&u.x, b = *(__half2*)&u.y;
    float2 fa = __half22float2(a), fb = __half22float2(b);
    return make_float4(fa.x, fa.y, fb.x, fb.y);
}

// ---------------------------------------------------------------------------
// Folded constants, staged on device (by proj2 block (0,0)) then copied into
// __constant__ via stream-ordered memcpyToSymbolAsync.
// ---------------------------------------------------------------------------
struct CParams {
    float4 w1[128];                         // w_w1 [o][4g..4g+3]
    float4 A[16];                           // bn1 scale folded
    float4 T0[16], T1[16], T2[16], TB[16];  // A*pw2 cols, A*pb2 + b1
    float4 R0[16], R1[16], R2[16], RB[16];  // raw pw2 cols, raw pb2
    float a2[8], c2f[8];                    // y = relu(a2*acc + c2f)
    float w2[64];
    float wb2[8];
    float fw1[9], fb1[3];                   // folded p-MLP layer1
    float pad[4];
};
__device__ CParams g_stage;
__constant__ CParams c_P;

struct PrepArgs {
    const float *pw1, *pb1, *pbng, *pbnb, *pbnm, *pbnv, *pw2, *pb2;
    const float *bn1g, *bn1b, *bn1m, *bn1v, *w1, *wb1;
    const float *bn2g, *bn2b, *bn2m, *bn2v, *w2, *wb2;
};

__device__ __forceinline__ void do_prep(const PrepArgs& a, int t) {
    // t in [0, 256)
    if (t < 64) {
        float g  = a.bn1g[t] * rsqrtf(a.bn1v[t] + EPSF);
        float b1 = a.bn1b[t] - a.bn1m[t] * g;
        float r0 = a.pw2[t * 3 + 0], r1 = a.pw2[t * 3 + 1], r2 = a.pw2[t * 3 + 2];
        float rb = a.pb2[t];
        ((float*)g_stage.A )[t] = g;
        ((float*)g_stage.T0)[t] = g * r0;
        ((float*)g_stage.T1)[t] = g * r1;
        ((float*)g_stage.T2)[t] = g * r2;
        ((float*)g_stage.TB)[t] = g * rb + b1;
        ((float*)g_stage.R0)[t] = r0;
        ((float*)g_stage.R1)[t] = r1;
        ((float*)g_stage.R2)[t] = r2;
        ((float*)g_stage.RB)[t] = rb;
        g_stage.w2[t] = a.w2[t];
    }
    for (int i = t; i < 512; i += 256) ((float*)g_stage.w1)[i] = a.w1[i];
    if (t < 8) {
        float a2 = a.bn2g[t] * rsqrtf(a.bn2v[t] + EPSF);
        g_stage.a2[t]  = a2;
        g_stage.c2f[t] = a2 * a.wb1[t] + (a.bn2b[t] - a.bn2m[t] * a2);
        g_stage.wb2[t] = a.wb2[t];
    }
    if (t < 3) {
        float pa = a.pbng[t] * rsqrtf(a.pbnv[t] + EPSF);
        g_stage.fw1[t * 3 + 0] = pa * a.pw1[t * 3 + 0];
        g_stage.fw1[t * 3 + 1] = pa * a.pw1[t * 3 + 1];
        g_stage.fw1[t * 3 + 2] = pa * a.pw1[t * 3 + 2];
        g_stage.fb1[t] = pa * a.pb1[t] + (a.pbnb[t] - a.pbnm[t] * pa);
    }
}

// ---------------------------------------------------------------------------
// Kernel A: q/k/v projection, fp16 output. Block = 64 points, specialized per
// q/k/v via blockIdx.y. Thread = (4 out channels, 4 points).
// Block (0,0) additionally folds the attn constants into g_stage.
// ---------------------------------------------------------------------------
__global__ __launch_bounds__(256) void proj2(
    const float* __restrict__ x,
    const float* __restrict__ Wq, const float* __restrict__ bq,
    const float* __restrict__ Wk, const float* __restrict__ bk,
    const float* __restrict__ Wv, const float* __restrict__ bv,
    PrepArgs pa, int N)
{
    const float* W; const float* b; __half2* dst;
    if (blockIdx.y == 0)      { W = Wq; b = bq; dst = g_xq; }
    else if (blockIdx.y == 1) { W = Wk; b = bk; dst = g_xk; }
    else                      { W = Wv; b = bv; dst = g_xv; }

    __shared__ __align__(16) float Wt[64 * 68];
    __shared__ __align__(16) float xs[64 * 64];
    int t = threadIdx.x;

    if (blockIdx.x == 0 && blockIdx.y == 0)
        do_prep(pa, t);

    for (int i = t; i < 4096; i += 256) {
        int o = i >> 6, c = i & 63;
        Wt[c * 68 + o] = W[i];
    }
    int tile0 = blockIdx.x * 64;
    for (int i = t; i < 1024; i += 256) {
        int f = i * 4;
        int pl = f >> 6, c = f & 63;
        int pt = tile0 + pl; pt = (pt < N) ? pt : N - 1;
        *(float4*)&xs[f] = *(const float4*)&x[(size_t)pt * 64 + c];
    }
    __syncthreads();

    int og = t & 15, pg = t >> 4;
    int o0 = og * 4;
    float4 bias = *(const float4*)&b[o0];

    float acc[4][4];
    #pragma unroll
    for (int a = 0; a < 4; a++)
        #pragma unroll
        for (int bb = 0; bb < 4; bb++) acc[a][bb] = 0.f;

    #pragma unroll
    for (int c4 = 0; c4 < 16; c4++) {
        float4 wv[4];
        #pragma unroll
        for (int k = 0; k < 4; k++)
            wv[k] = *(const float4*)&Wt[(4 * c4 + k) * 68 + o0];
        #pragma unroll
        for (int pp = 0; pp < 4; pp++) {
            float4 x4 = *(const float4*)&xs[(pg * 4 + pp) * 64 + 4 * c4];
            acc[pp][0] = fmaf(x4.x, wv[0].x, fmaf(x4.y, wv[1].x, fmaf(x4.z, wv[2].x, fmaf(x4.w, wv[3].x, acc[pp][0]))));
            acc[pp][1] = fmaf(x4.x, wv[0].y, fmaf(x4.y, wv[1].y, fmaf(x4.z, wv[2].y, fmaf(x4.w, wv[3].y, acc[pp][1]))));
            acc[pp][2] = fmaf(x4.x, wv[0].z, fmaf(x4.y, wv[1].z, fmaf(x4.z, wv[2].z, fmaf(x4.w, wv[3].z, acc[pp][2]))));
            acc[pp][3] = fmaf(x4.x, wv[0].w, fmaf(x4.y, wv[1].w, fmaf(x4.z, wv[2].w, fmaf(x4.w, wv[3].w, acc[pp][3]))));
        }
    }
    #pragma unroll
    for (int pp = 0; pp < 4; pp++) {
        int pt = tile0 + pg * 4 + pp;
        if (pt < N) {
            __half2 h0 = __floats2half2_rn(acc[pp][0] + bias.x, acc[pp][1] + bias.y);
            __half2 h1 = __floats2half2_rn(acc[pp][2] + bias.z, acc[pp][3] + bias.w);
            uint2 st;
            st.x = *(unsigned int*)&h0;
            st.y = *(unsigned int*)&h1;
            *(uint2*)(dst + (size_t)pt * 32 + og * 2) = st;
        }
    }
}

// ---------------------------------------------------------------------------
// Kernel B: fused attention. Block = 8 points, 128 threads, warp-local.
// __launch_bounds__(128,12): cap regs ~42 -> 12 blocks/SM = 75% occupancy.
// ---------------------------------------------------------------------------
__global__ __launch_bounds__(128, 12) void attn2(
    const float* __restrict__ p, const int* __restrict__ idx,
    float* __restrict__ out, int N)
{
    __shared__ __align__(16) float4 vbuf[8][16][16];
    __shared__ __align__(16) float  wex[8][16][12];
    __shared__ __align__(16) float  Hs[8][3][8];
    __shared__ float hs[8][16][4];
    __shared__ int   idxs[8][16];
    __shared__ float pns[8][4];

    int t = threadIdx.x, lane = t & 31, wid = t >> 5;
    int n0 = blockIdx.x * 8;

    int lpA = t >> 4, sub = t & 15;
    int nA  = n0 + lpA;
    int nAc = (nA < N) ? nA : N - 1;

    // prologue: indices, center coords, h-MLP
    int id0 = idx[(size_t)nAc * 16 + sub];
    id0 = (id0 < 0) ? 0 : ((id0 >= N) ? N - 1 : id0);
    idxs[lpA][sub] = id0;
    if (lane < 6) {
        int pp = wid * 2 + lane / 3, d = lane % 3;
        int np = n0 + pp; np = (np < N) ? np : N - 1;
        pns[pp][d] = p[(size_t)np * 3 + d];
    }
    __syncwarp();
    {
        float prx = p[(size_t)id0 * 3 + 0] - pns[lpA][0];
        float pry = p[(size_t)id0 * 3 + 1] - pns[lpA][1];
        float prz = p[(size_t)id0 * 3 + 2] - pns[lpA][2];
        hs[lpA][sub][0] = fmaxf(fmaf(prx, c_P.fw1[0], fmaf(pry, c_P.fw1[1], fmaf(prz, c_P.fw1[2], c_P.fb1[0]))), 0.f);
        hs[lpA][sub][1] = fmaxf(fmaf(prx, c_P.fw1[3], fmaf(pry, c_P.fw1[4], fmaf(prz, c_P.fw1[5], c_P.fb1[1]))), 0.f);
        hs[lpA][sub][2] = fmaxf(fmaf(prx, c_P.fw1[6], fmaf(pry, c_P.fw1[7], fmaf(prz, c_P.fw1[8], c_P.fb1[2]))), 0.f);
    }
    float4 Ac = c_P.A[sub];
    float4 T0 = c_P.T0[sub], T1 = c_P.T1[sub], T2 = c_P.T2[sub];
    float4 TBc = c_P.TB[sub];
    float4 xq4 = ldg_h4(g_xq, (size_t)nAc, sub);
    float4 TBm = make_float4(TBc.x - Ac.x * xq4.x, TBc.y - Ac.y * xq4.y,
                             TBc.z - Ac.z * xq4.z, TBc.w - Ac.w * xq4.w);
    __syncwarp();

    // ---- Phase A: v = relu(A*xk + T.h + TBm) -> swizzled vbuf --------------
    #pragma unroll
    for (int j = 0; j < 16; j++) {
        int id = idxs[lpA][j];
        float h0 = hs[lpA][j][0], h1 = hs[lpA][j][1], h2 = hs[lpA][j][2];
        float4 xk4 = ldg_h4(g_xk, (size_t)id, sub);
        float4 v;
        v.x = fmaxf(fmaf(Ac.x, xk4.x, fmaf(T2.x, h2, fmaf(T1.x, h1, fmaf(T0.x, h0, TBm.x)))), 0.f);
        v.y = fmaxf(fmaf(Ac.y, xk4.y, fmaf(T2.y, h2, fmaf(T1.y, h1, fmaf(T0.y, h0, TBm.y)))), 0.f);
        v.z = fmaxf(fmaf(Ac.z, xk4.z, fmaf(T2.z, h2, fmaf(T1.z, h1, fmaf(T0.z, h0, TBm.z)))), 0.f);
        v.w = fmaxf(fmaf(Ac.w, xk4.w, fmaf(T2.w, h2, fmaf(T1.w, h1, fmaf(T0.w, h0, TBm.w)))), 0.f);
        vbuf[lpA][j][(sub + j) & 15] = v;
    }
    __syncwarp();

    // ---- Phase B: 64->8 projection + BN2 + w2 + softmax --------------------
    int lpB = wid * 2 + (lane >> 4), jj = lane & 15;
    {
        float acc[8];
        #pragma unroll
        for (int o = 0; o < 8; o++) acc[o] = 0.f;
        #pragma unroll
        for (int g = 0; g < 16; g++) {
            float4 v4 = vbuf[lpB][jj][(g + jj) & 15];
            #pragma unroll
            for (int o = 0; o < 8; o++) {
                float4 w = c_P.w1[o * 16 + g];
                acc[o] = fmaf(w.x, v4.x, fmaf(w.y, v4.y, fmaf(w.z, v4.z, fmaf(w.w, v4.w, acc[o]))));
            }
        }
        float y[8];
        #pragma unroll
        for (int o = 0; o < 8; o++)
            y[o] = fmaxf(fmaf(c_P.a2[o], acc[o], c_P.c2f[o]), 0.f);
        #pragma unroll
        for (int u = 0; u < 8; u++) {
            float s = c_P.wb2[u];
            #pragma unroll
            for (int o = 0; o < 8; o++) s = fmaf(y[o], c_P.w2[u * 8 + o], s);
            acc[u] = s;                       // reuse acc as z
        }
        #pragma unroll
        for (int u = 0; u < 8; u++) {
            float z = acc[u];
            float m = z;
            m = fmaxf(m, __shfl_xor_sync(0xffffffffu, m, 1));
            m = fmaxf(m, __shfl_xor_sync(0xffffffffu, m, 2));
            m = fmaxf(m, __shfl_xor_sync(0xffffffffu, m, 4));
            m = fmaxf(m, __shfl_xor_sync(0xffffffffu, m, 8));
            float ev = __expf(z - m);
            float s = ev;
            s += __shfl_xor_sync(0xffffffffu, s, 1);
            s += __shfl_xor_sync(0xffffffffu, s, 2);
            s += __shfl_xor_sync(0xffffffffu, s, 4);
            s += __shfl_xor_sync(0xffffffffu, s, 8);
            wex[lpB][jj][u] = ev * __frcp_rn(s);   // store immediately, keep regs low
        }
    }
    __syncwarp();

    // ---- H[u] = sum_j h_j * wex_j[u]  (per point, 3x8 values) --------------
    if (sub < 8) {
        float H0 = 0.f, H1 = 0.f, H2 = 0.f;
        #pragma unroll
        for (int j = 0; j < 16; j++) {
            float w = wex[lpA][j][sub];
            H0 = fmaf(hs[lpA][j][0], w, H0);
            H1 = fmaf(hs[lpA][j][1], w, H1);
            H2 = fmaf(hs[lpA][j][2], w, H2);
        }
        Hs[lpA][0][sub] = H0;
        Hs[lpA][1][sub] = H1;
        Hs[lpA][2][sub] = H2;
    }
    __syncwarp();

    // ---- Phase 2: out_c = pw2_c.H[u] + pb2_c + sum_j xv_jc * wex_j[u] ------
    float4 q0 = c_P.R0[sub], q1 = c_P.R1[sub], q2 = c_P.R2[sub], qb = c_P.RB[sub];
    int u0 = (sub & 1) * 4;
    float4 H0v = *(const float4*)&Hs[lpA][0][u0];
    float4 H1v = *(const float4*)&Hs[lpA][1][u0];
    float4 H2v = *(const float4*)&Hs[lpA][2][u0];
    float bx = fmaf(q0.x, H0v.x, fmaf(q1.x, H1v.x, fmaf(q2.x, H2v.x, qb.x)));
    float by = fmaf(q0.y, H0v.y, fmaf(q1.y, H1v.y, fmaf(q2.y, H2v.y, qb.y)));
    float bz = fmaf(q0.z, H0v.z, fmaf(q1.z, H1v.z, fmaf(q2.z, H2v.z, qb.z)));
    float bw = fmaf(q0.w, H0v.w, fmaf(q1.w, H1v.w, fmaf(q2.w, H2v.w, qb.w)));

    float ox = 0.f, oy = 0.f, oz = 0.f, ow = 0.f;
    #pragma unroll
    for (int j = 0; j < 16; j++) {
        int id = idxs[lpA][j];
        float4 xv4 = ldg_h4(g_xv, (size_t)id, sub);
        float4 wn4 = *(const float4*)&wex[lpA][j][u0];
        ox = fmaf(xv4.x, wn4.x, ox);
        oy = fmaf(xv4.y, wn4.y, oy);
        oz = fmaf(xv4.z, wn4.z, oz);
        ow = fmaf(xv4.w, wn4.w, ow);
    }
    if (nA < N)
        *(float4*)&out[(size_t)nA * 64 + sub * 4] =
            make_float4(ox + bx, oy + by, oz + bz, ow + bw);
}

// ---------------------------------------------------------------------------
extern "C" void kernel_launch(void* const* d_in, const int* in_sizes, int n_in,
                              void* d_out, int out_size)
{
    const float* p   = (const float*)d_in[0];
    const float* x   = (const float*)d_in[1];
    const int* idx   = (const int*)d_in[2];
    const float* Wq  = (const float*)d_in[3];
    const float* bq  = (const float*)d_in[4];
    const float* Wk  = (const float*)d_in[5];
    const float* bk  = (const float*)d_in[6];
    const float* Wv  = (const float*)d_in[7];
    const float* bv  = (const float*)d_in[8];

    PrepArgs pa;
    pa.pw1  = (const float*)d_in[9];
    pa.pb1  = (const float*)d_in[10];
    pa.pbng = (const float*)d_in[11];
    pa.pbnb = (const float*)d_in[12];
    pa.pbnm = (const float*)d_in[13];
    pa.pbnv = (const float*)d_in[14];
    pa.pw2  = (const float*)d_in[15];
    pa.pb2  = (const float*)d_in[16];
    pa.bn1g = (const float*)d_in[17];
    pa.bn1b = (const float*)d_in[18];
    pa.bn1m = (const float*)d_in[19];
    pa.bn1v = (const float*)d_in[20];
    pa.w1   = (const float*)d_in[21];
    pa.wb1  = (const float*)d_in[22];
    pa.bn2g = (const float*)d_in[23];
    pa.bn2b = (const float*)d_in[24];
    pa.bn2m = (const float*)d_in[25];
    pa.bn2v = (const float*)d_in[26];
    pa.w2   = (const float*)d_in[27];
    pa.wb2  = (const float*)d_in[28];

    int N = in_sizes[1] / 64;

    dim3 pgrid((N + 63) / 64, 3);
    proj2<<<pgrid, 256>>>(x, Wq, bq, Wk, bk, Wv, bv, pa, N);

    void* sp = nullptr;
    cudaGetSymbolAddress(&sp, g_stage);
    cudaMemcpyToSymbolAsync(c_P, sp, sizeof(CParams), 0,
                            cudaMemcpyDeviceToDevice, 0);

    attn2<<<(N + 7) / 8, 128>>>(p, idx, (float*)d_out, N);
}

// round 12
// speedup vs baseline: 1.1610x; 1.1610x over previous
#include <cuda_runtime.h>
#include <cuda_fp16.h>

#define NMAX 100000
#define EPSF 1e-5f

// q/k/v projection scratch in fp16 (device globals: allocation-free).
// Row = 32 half2 = 64 channels = 128 bytes (one L2/L1 line per row).
__device__ __half2 g_xq[NMAX * 32];
__device__ __half2 g_xk[NMAX * 32];
__device__ __half2 g_xv[NMAX * 32];

__device__ __forceinline__ float4 ldg_h4(const __half2* __restrict__ base,
                                         size_t row, int sub) {
    uint2 u = *(const uint2*)(base + row * 32 + sub * 2);
    __half2 a = *(__half2*)&u.x, b = *(__half2*)&u.y;
    float2 fa = __half22float2(a), fb = __half22float2(b);
    return make_float4(fa.x, fa.y, fb.x, fb.y);
}

// ---------------------------------------------------------------------------
// Folded constants, staged on device (by proj2 block (0,0)) then copied into
// __constant__ via stream-ordered memcpyToSymbolAsync.
// ---------------------------------------------------------------------------
struct CParams {
    float4 w1[128];                         // w_w1 [o][4g..4g+3]
    float4 A[16];                           // bn1 scale folded
    float4 T0[16], T1[16], T2[16], TB[16];  // A*pw2 cols, A*pb2 + b1
    float4 R0[16], R1[16], R2[16], RB[16];  // raw pw2 cols, raw pb2
    float a2[8], c2f[8];                    // y = relu(a2*acc + c2f)
    float w2[64];
    float wb2[8];
    float fw1[9], fb1[3];                   // folded p-MLP layer1
    float pad[4];
};
__device__ CParams g_stage;
__constant__ CParams c_P;

struct PrepArgs {
    const float *pw1, *pb1, *pbng, *pbnb, *pbnm, *pbnv, *pw2, *pb2;
    const float *bn1g, *bn1b, *bn1m, *bn1v, *w1, *wb1;
    const float *bn2g, *bn2b, *bn2m, *bn2v, *w2, *wb2;
};

__device__ __forceinline__ void do_prep(const PrepArgs& a, int t) {
    // t in [0, 256)
    if (t < 64) {
        float g  = a.bn1g[t] * rsqrtf(a.bn1v[t] + EPSF);
        float b1 = a.bn1b[t] - a.bn1m[t] * g;
        float r0 = a.pw2[t * 3 + 0], r1 = a.pw2[t * 3 + 1], r2 = a.pw2[t * 3 + 2];
        float rb = a.pb2[t];
        ((float*)g_stage.A )[t] = g;
        ((float*)g_stage.T0)[t] = g * r0;
        ((float*)g_stage.T1)[t] = g * r1;
        ((float*)g_stage.T2)[t] = g * r2;
        ((float*)g_stage.TB)[t] = g * rb + b1;
        ((float*)g_stage.R0)[t] = r0;
        ((float*)g_stage.R1)[t] = r1;
        ((float*)g_stage.R2)[t] = r2;
        ((float*)g_stage.RB)[t] = rb;
        g_stage.w2[t] = a.w2[t];
    }
    for (int i = t; i < 512; i += 256) ((float*)g_stage.w1)[i] = a.w1[i];
    if (t < 8) {
        float a2 = a.bn2g[t] * rsqrtf(a.bn2v[t] + EPSF);
        g_stage.a2[t]  = a2;
        g_stage.c2f[t] = a2 * a.wb1[t] + (a.bn2b[t] - a.bn2m[t] * a2);
        g_stage.wb2[t] = a.wb2[t];
    }
    if (t < 3) {
        float pa = a.pbng[t] * rsqrtf(a.pbnv[t] + EPSF);
        g_stage.fw1[t * 3 + 0] = pa * a.pw1[t * 3 + 0];
        g_stage.fw1[t * 3 + 1] = pa * a.pw1[t * 3 + 1];
        g_stage.fw1[t * 3 + 2] = pa * a.pw1[t * 3 + 2];
        g_stage.fb1[t] = pa * a.pb1[t] + (a.pbnb[t] - a.pbnm[t] * pa);
    }
}

// ---------------------------------------------------------------------------
// Kernel A: q/k/v projection, fp16 output. Block = 64 points, specialized per
// q/k/v via blockIdx.y. Thread = (4 out channels, 4 points).
// Block (0,0) additionally folds the attn constants into g_stage.
// ---------------------------------------------------------------------------
__global__ __launch_bounds__(256) void proj2(
    const float* __restrict__ x,
    const float* __restrict__ Wq, const float* __restrict__ bq,
    const float* __restrict__ Wk, const float* __restrict__ bk,
    const float* __restrict__ Wv, const float* __restrict__ bv,
    PrepArgs pa, int N)
{
    const float* W; const float* b; __half2* dst;
    if (blockIdx.y == 0)      { W = Wq; b = bq; dst = g_xq; }
    else if (blockIdx.y == 1) { W = Wk; b = bk; dst = g_xk; }
    else                      { W = Wv; b = bv; dst = g_xv; }

    __shared__ __align__(16) float Wt[64 * 68];
    __shared__ __align__(16) float xs[64 * 64];
    int t = threadIdx.x;

    if (blockIdx.x == 0 && blockIdx.y == 0)
        do_prep(pa, t);

    for (int i = t; i < 4096; i += 256) {
        int o = i >> 6, c = i & 63;
        Wt[c * 68 + o] = W[i];
    }
    int tile0 = blockIdx.x * 64;
    for (int i = t; i < 1024; i += 256) {
        int f = i * 4;
        int pl = f >> 6, c = f & 63;
        int pt = tile0 + pl; pt = (pt < N) ? pt : N - 1;
        *(float4*)&xs[f] = *(const float4*)&x[(size_t)pt * 64 + c];
    }
    __syncthreads();

    int og = t & 15, pg = t >> 4;
    int o0 = og * 4;
    float4 bias = *(const float4*)&b[o0];

    float acc[4][4];
    #pragma unroll
    for (int a = 0; a < 4; a++)
        #pragma unroll
        for (int bb = 0; bb < 4; bb++) acc[a][bb] = 0.f;

    #pragma unroll
    for (int c4 = 0; c4 < 16; c4++) {
        float4 wv[4];
        #pragma unroll
        for (int k = 0; k < 4; k++)
            wv[k] = *(const float4*)&Wt[(4 * c4 + k) * 68 + o0];
        #pragma unroll
        for (int pp = 0; pp < 4; pp++) {
            float4 x4 = *(const float4*)&xs[(pg * 4 + pp) * 64 + 4 * c4];
            acc[pp][0] = fmaf(x4.x, wv[0].x, fmaf(x4.y, wv[1].x, fmaf(x4.z, wv[2].x, fmaf(x4.w, wv[3].x, acc[pp][0]))));
            acc[pp][1] = fmaf(x4.x, wv[0].y, fmaf(x4.y, wv[1].y, fmaf(x4.z, wv[2].y, fmaf(x4.w, wv[3].y, acc[pp][1]))));
            acc[pp][2] = fmaf(x4.x, wv[0].z, fmaf(x4.y, wv[1].z, fmaf(x4.z, wv[2].z, fmaf(x4.w, wv[3].z, acc[pp][2]))));
            acc[pp][3] = fmaf(x4.x, wv[0].w, fmaf(x4.y, wv[1].w, fmaf(x4.z, wv[2].w, fmaf(x4.w, wv[3].w, acc[pp][3]))));
        }
    }
    #pragma unroll
    for (int pp = 0; pp < 4; pp++) {
        int pt = tile0 + pg * 4 + pp;
        if (pt < N) {
            __half2 h0 = __floats2half2_rn(acc[pp][0] + bias.x, acc[pp][1] + bias.y);
            __half2 h1 = __floats2half2_rn(acc[pp][2] + bias.z, acc[pp][3] + bias.w);
            uint2 st;
            st.x = *(unsigned int*)&h0;
            st.y = *(unsigned int*)&h1;
            *(uint2*)(dst + (size_t)pt * 32 + og * 2) = st;
        }
    }
}

// ---------------------------------------------------------------------------
// Kernel B: fused attention. Block = 8 points, 128 threads, warp-local.
// vbuf stored as fp16 (uint2 = 2x half2) -> 16KB; block smem ~25KB ->
// 8 blocks/SM (50% occupancy). __launch_bounds__(128,8): regs<=64, no spills.
// ---------------------------------------------------------------------------
__global__ __launch_bounds__(128, 8) void attn2(
    const float* __restrict__ p, const int* __restrict__ idx,
    float* __restrict__ out, int N)
{
    __shared__ __align__(16) uint2  vbuf[8][16][16];   // fp16 v, swizzled
    __shared__ __align__(16) float  wex[8][16][12];
    __shared__ __align__(16) float  Hs[8][3][8];
    __shared__ float hs[8][16][4];
    __shared__ int   idxs[8][16];
    __shared__ float pns[8][4];

    int t = threadIdx.x, lane = t & 31, wid = t >> 5;
    int n0 = blockIdx.x * 8;

    int lpA = t >> 4, sub = t & 15;
    int nA  = n0 + lpA;
    int nAc = (nA < N) ? nA : N - 1;

    // prologue: indices, center coords, h-MLP
    int id0 = idx[(size_t)nAc * 16 + sub];
    id0 = (id0 < 0) ? 0 : ((id0 >= N) ? N - 1 : id0);
    idxs[lpA][sub] = id0;
    if (lane < 6) {
        int pp = wid * 2 + lane / 3, d = lane % 3;
        int np = n0 + pp; np = (np < N) ? np : N - 1;
        pns[pp][d] = p[(size_t)np * 3 + d];
    }
    __syncwarp();
    {
        float prx = p[(size_t)id0 * 3 + 0] - pns[lpA][0];
        float pry = p[(size_t)id0 * 3 + 1] - pns[lpA][1];
        float prz = p[(size_t)id0 * 3 + 2] - pns[lpA][2];
        hs[lpA][sub][0] = fmaxf(fmaf(prx, c_P.fw1[0], fmaf(pry, c_P.fw1[1], fmaf(prz, c_P.fw1[2], c_P.fb1[0]))), 0.f);
        hs[lpA][sub][1] = fmaxf(fmaf(prx, c_P.fw1[3], fmaf(pry, c_P.fw1[4], fmaf(prz, c_P.fw1[5], c_P.fb1[1]))), 0.f);
        hs[lpA][sub][2] = fmaxf(fmaf(prx, c_P.fw1[6], fmaf(pry, c_P.fw1[7], fmaf(prz, c_P.fw1[8], c_P.fb1[2]))), 0.f);
    }
    float4 Ac = c_P.A[sub];
    float4 T0 = c_P.T0[sub], T1 = c_P.T1[sub], T2 = c_P.T2[sub];
    float4 TBc = c_P.TB[sub];
    float4 xq4 = ldg_h4(g_xq, (size_t)nAc, sub);
    float4 TBm = make_float4(TBc.x - Ac.x * xq4.x, TBc.y - Ac.y * xq4.y,
                             TBc.z - Ac.z * xq4.z, TBc.w - Ac.w * xq4.w);
    __syncwarp();

    // ---- Phase A: v = relu(A*xk + T.h + TBm) -> swizzled fp16 vbuf ---------
    #pragma unroll
    for (int j = 0; j < 16; j++) {
        int id = idxs[lpA][j];
        float h0 = hs[lpA][j][0], h1 = hs[lpA][j][1], h2 = hs[lpA][j][2];
        float4 xk4 = ldg_h4(g_xk, (size_t)id, sub);
        float vx = fmaxf(fmaf(Ac.x, xk4.x, fmaf(T2.x, h2, fmaf(T1.x, h1, fmaf(T0.x, h0, TBm.x)))), 0.f);
        float vy = fmaxf(fmaf(Ac.y, xk4.y, fmaf(T2.y, h2, fmaf(T1.y, h1, fmaf(T0.y, h0, TBm.y)))), 0.f);
        float vz = fmaxf(fmaf(Ac.z, xk4.z, fmaf(T2.z, h2, fmaf(T1.z, h1, fmaf(T0.z, h0, TBm.z)))), 0.f);
        float vw = fmaxf(fmaf(Ac.w, xk4.w, fmaf(T2.w, h2, fmaf(T1.w, h1, fmaf(T0.w, h0, TBm.w)))), 0.f);
        __half2 ha = __floats2half2_rn(vx, vy);
        __half2 hb = __floats2half2_rn(vz, vw);
        uint2 st;
        st.x = *(unsigned int*)&ha;
        st.y = *(unsigned int*)&hb;
        vbuf[lpA][j][(sub + j) & 15] = st;
    }
    __syncwarp();

    // ---- Phase B: 64->8 projection + BN2 + w2 + softmax --------------------
    int lpB = wid * 2 + (lane >> 4), jj = lane & 15;
    {
        float acc[8];
        #pragma unroll
        for (int o = 0; o < 8; o++) acc[o] = 0.f;
        #pragma unroll
        for (int g = 0; g < 16; g++) {
            uint2 u = vbuf[lpB][jj][(g + jj) & 15];
            float2 fa = __half22float2(*(__half2*)&u.x);
            float2 fb = __half22float2(*(__half2*)&u.y);
            #pragma unroll
            for (int o = 0; o < 8; o++) {
                float4 w = c_P.w1[o * 16 + g];
                acc[o] = fmaf(w.x, fa.x, fmaf(w.y, fa.y, fmaf(w.z, fb.x, fmaf(w.w, fb.y, acc[o]))));
            }
        }
        float y[8];
        #pragma unroll
        for (int o = 0; o < 8; o++)
            y[o] = fmaxf(fmaf(c_P.a2[o], acc[o], c_P.c2f[o]), 0.f);
        #pragma unroll
        for (int u = 0; u < 8; u++) {
            float s = c_P.wb2[u];
            #pragma unroll
            for (int o = 0; o < 8; o++) s = fmaf(y[o], c_P.w2[u * 8 + o], s);
            acc[u] = s;                       // reuse acc as z
        }
        #pragma unroll
        for (int u = 0; u < 8; u++) {
            float z = acc[u];
            float m = z;
            m = fmaxf(m, __shfl_xor_sync(0xffffffffu, m, 1));
            m = fmaxf(m, __shfl_xor_sync(0xffffffffu, m, 2));
            m = fmaxf(m, __shfl_xor_sync(0xffffffffu, m, 4));
            m = fmaxf(m, __shfl_xor_sync(0xffffffffu, m, 8));
            float ev = __expf(z - m);
            float s = ev;
            s += __shfl_xor_sync(0xffffffffu, s, 1);
            s += __shfl_xor_sync(0xffffffffu, s, 2);
            s += __shfl_xor_sync(0xffffffffu, s, 4);
            s += __shfl_xor_sync(0xffffffffu, s, 8);
            wex[lpB][jj][u] = ev * __frcp_rn(s);
        }
    }
    __syncwarp();

    // ---- H[u] = sum_j h_j * wex_j[u]  (per point, 3x8 values) --------------
    if (sub < 8) {
        float H0 = 0.f, H1 = 0.f, H2 = 0.f;
        #pragma unroll
        for (int j = 0; j < 16; j++) {
            float w = wex[lpA][j][sub];
            H0 = fmaf(hs[lpA][j][0], w, H0);
            H1 = fmaf(hs[lpA][j][1], w, H1);
            H2 = fmaf(hs[lpA][j][2], w, H2);
        }
        Hs[lpA][0][sub] = H0;
        Hs[lpA][1][sub] = H1;
        Hs[lpA][2][sub] = H2;
    }
    __syncwarp();

    // ---- Phase 2: out_c = pw2_c.H[u] + pb2_c + sum_j xv_jc * wex_j[u] ------
    float4 q0 = c_P.R0[sub], q1 = c_P.R1[sub], q2 = c_P.R2[sub], qb = c_P.RB[sub];
    int u0 = (sub & 1) * 4;
    float4 H0v = *(const float4*)&Hs[lpA][0][u0];
    float4 H1v = *(const float4*)&Hs[lpA][1][u0];
    float4 H2v = *(const float4*)&Hs[lpA][2][u0];
    float bx = fmaf(q0.x, H0v.x, fmaf(q1.x, H1v.x, fmaf(q2.x, H2v.x, qb.x)));
    float by = fmaf(q0.y, H0v.y, fmaf(q1.y, H1v.y, fmaf(q2.y, H2v.y, qb.y)));
    float bz = fmaf(q0.z, H0v.z, fmaf(q1.z, H1v.z, fmaf(q2.z, H2v.z, qb.z)));
    float bw = fmaf(q0.w, H0v.w, fmaf(q1.w, H1v.w, fmaf(q2.w, H2v.w, qb.w)));

    float ox = 0.f, oy = 0.f, oz = 0.f, ow = 0.f;
    #pragma unroll
    for (int j = 0; j < 16; j++) {
        int id = idxs[lpA][j];
        float4 xv4 = ldg_h4(g_xv, (size_t)id, sub);
        float4 wn4 = *(const float4*)&wex[lpA][j][u0];
        ox = fmaf(xv4.x, wn4.x, ox);
        oy = fmaf(xv4.y, wn4.y, oy);
        oz = fmaf(xv4.z, wn4.z, oz);
        ow = fmaf(xv4.w, wn4.w, ow);
    }
    if (nA < N)
        *(float4*)&out[(size_t)nA * 64 + sub * 4] =
            make_float4(ox + bx, oy + by, oz + bz, ow + bw);
}

// ---------------------------------------------------------------------------
extern "C" void kernel_launch(void* const* d_in, const int* in_sizes, int n_in,
                              void* d_out, int out_size)
{
    const float* p   = (const float*)d_in[0];
    const float* x   = (const float*)d_in[1];
    const int* idx   = (const int*)d_in[2];
    const float* Wq  = (const float*)d_in[3];
    const float* bq  = (const float*)d_in[4];
    const float* Wk  = (const float*)d_in[5];
    const float* bk  = (const float*)d_in[6];
    const float* Wv  = (const float*)d_in[7];
    const float* bv  = (const float*)d_in[8];

    PrepArgs pa;
    pa.pw1  = (const float*)d_in[9];
    pa.pb1  = (const float*)d_in[10];
    pa.pbng = (const float*)d_in[11];
    pa.pbnb = (const float*)d_in[12];
    pa.pbnm = (const float*)d_in[13];
    pa.pbnv = (const float*)d_in[14];
    pa.pw2  = (const float*)d_in[15];
    pa.pb2  = (const float*)d_in[16];
    pa.bn1g = (const float*)d_in[17];
    pa.bn1b = (const float*)d_in[18];
    pa.bn1m = (const float*)d_in[19];
    pa.bn1v = (const float*)d_in[20];
    pa.w1   = (const float*)d_in[21];
    pa.wb1  = (const float*)d_in[22];
    pa.bn2g = (const float*)d_in[23];
    pa.bn2b = (const float*)d_in[24];
    pa.bn2m = (const float*)d_in[25];
    pa.bn2v = (const float*)d_in[26];
    pa.w2   = (const float*)d_in[27];
    pa.wb2  = (const float*)d_in[28];

    int N = in_sizes[1] / 64;

    dim3 pgrid((N + 63) / 64, 3);
    proj2<<<pgrid, 256>>>(x, Wq, bq, Wk, bk, Wv, bv, pa, N);

    void* sp = nullptr;
    cudaGetSymbolAddress(&sp, g_stage);
    cudaMemcpyToSymbolAsync(c_P, sp, sizeof(CParams), 0,
                            cudaMemcpyDeviceToDevice, 0);

    attn2<<<(N + 7) / 8, 128>>>(p, idx, (float*)d_out, N);
}

// round 13
// speedup vs baseline: 1.3147x; 1.1324x over previous
#include <cuda_runtime.h>
#include <cuda_fp16.h>

#define NMAX 100000
#define EPSF 1e-5f

typedef unsigned long long u64;

__device__ __forceinline__ u64 pk2(float lo, float hi) {
    u64 r; asm("mov.b64 %0, {%1,%2};" : "=l"(r) : "f"(lo), "f"(hi)); return r;
}
__device__ __forceinline__ float2 upk2(u64 v) {
    float2 r; asm("mov.b64 {%0,%1}, %2;" : "=f"(r.x), "=f"(r.y) : "l"(v)); return r;
}
__device__ __forceinline__ u64 fma2(u64 a, u64 b, u64 c) {
    u64 d; asm("fma.rn.f32x2 %0, %1, %2, %3;" : "=l"(d) : "l"(a), "l"(b), "l"(c)); return d;
}

// q/k/v projection scratch in fp16 (device globals: allocation-free).
__device__ __half2 g_xq[NMAX * 32];
__device__ __half2 g_xk[NMAX * 32];
__device__ __half2 g_xv[NMAX * 32];

__device__ __forceinline__ float4 ldg_h4(const __half2* __restrict__ base,
                                         size_t row, int sub) {
    uint2 u = *(const uint2*)(base + row * 32 + sub * 2);
    __half2 a = *(__half2*)&u.x, b = *(__half2*)&u.y;
    float2 fa = __half22float2(a), fb = __half22float2(b);
    return make_float4(fa.x, fa.y, fb.x, fb.y);
}

// ---------------------------------------------------------------------------
// Folded constants, staged on device (by proj2 block (0,0)) then copied into
// __constant__ via stream-ordered memcpyToSymbolAsync.
// ---------------------------------------------------------------------------
struct CParams {
    float2 w1p[256];                        // [ch][opair]: (w1[2op][ch], w1[2op+1][ch])
    float4 A[16];                           // bn1 scale folded
    float4 T0[16], T1[16], T2[16], TB[16];  // A*pw2 cols, A*pb2 + b1
    float4 R0[16], R1[16], R2[16], RB[16];  // raw pw2 cols, raw pb2
    float a2[8], c2f[8];                    // y = relu(a2*acc + c2f)
    float w2[64];
    float wb2[8];
    float fw1[9], fb1[3];                   // folded p-MLP layer1
    float pad[4];
};
__device__ CParams g_stage;
__constant__ CParams c_P;

struct PrepArgs {
    const float *pw1, *pb1, *pbng, *pbnb, *pbnm, *pbnv, *pw2, *pb2;
    const float *bn1g, *bn1b, *bn1m, *bn1v, *w1, *wb1;
    const float *bn2g, *bn2b, *bn2m, *bn2v, *w2, *wb2;
};

__device__ __forceinline__ void do_prep(const PrepArgs& a, int t) {
    // t in [0, 256)
    if (t < 64) {
        float g  = a.bn1g[t] * rsqrtf(a.bn1v[t] + EPSF);
        float b1 = a.bn1b[t] - a.bn1m[t] * g;
        float r0 = a.pw2[t * 3 + 0], r1 = a.pw2[t * 3 + 1], r2 = a.pw2[t * 3 + 2];
        float rb = a.pb2[t];
        ((float*)g_stage.A )[t] = g;
        ((float*)g_stage.T0)[t] = g * r0;
        ((float*)g_stage.T1)[t] = g * r1;
        ((float*)g_stage.T2)[t] = g * r2;
        ((float*)g_stage.TB)[t] = g * rb + b1;
        ((float*)g_stage.R0)[t] = r0;
        ((float*)g_stage.R1)[t] = r1;
        ((float*)g_stage.R2)[t] = r2;
        ((float*)g_stage.RB)[t] = rb;
        g_stage.w2[t] = a.w2[t];
    }
    // w1 pairs: w1p[ch*4 + op] = (w1[2op][ch], w1[2op+1][ch])
    if (t < 256) {
        int op = t & 3, ch = t >> 2;
        g_stage.w1p[t] = make_float2(a.w1[(2 * op) * 64 + ch],
                                     a.w1[(2 * op + 1) * 64 + ch]);
    }
    if (t < 8) {
        float a2 = a.bn2g[t] * rsqrtf(a.bn2v[t] + EPSF);
        g_stage.a2[t]  = a2;
        g_stage.c2f[t] = a2 * a.wb1[t] + (a.bn2b[t] - a.bn2m[t] * a2);
        g_stage.wb2[t] = a.wb2[t];
    }
    if (t < 3) {
        float pa = a.pbng[t] * rsqrtf(a.pbnv[t] + EPSF);
        g_stage.fw1[t * 3 + 0] = pa * a.pw1[t * 3 + 0];
        g_stage.fw1[t * 3 + 1] = pa * a.pw1[t * 3 + 1];
        g_stage.fw1[t * 3 + 2] = pa * a.pw1[t * 3 + 2];
        g_stage.fb1[t] = pa * a.pb1[t] + (a.pbnb[t] - a.pbnm[t] * pa);
    }
}

// ---------------------------------------------------------------------------
// Kernel A: q/k/v projection, fp16 output, f32x2 packed math.
// ---------------------------------------------------------------------------
__global__ __launch_bounds__(256) void proj2(
    const float* __restrict__ x,
    const float* __restrict__ Wq, const float* __restrict__ bq,
    const float* __restrict__ Wk, const float* __restrict__ bk,
    const float* __restrict__ Wv, const float* __restrict__ bv,
    PrepArgs pa, int N)
{
    const float* W; const float* b; __half2* dst;
    if (blockIdx.y == 0)      { W = Wq; b = bq; dst = g_xq; }
    else if (blockIdx.y == 1) { W = Wk; b = bk; dst = g_xk; }
    else                      { W = Wv; b = bv; dst = g_xv; }

    __shared__ __align__(16) float Wt[64 * 68];
    __shared__ __align__(16) float xs[64 * 64];
    int t = threadIdx.x;

    if (blockIdx.x == 0 && blockIdx.y == 0)
        do_prep(pa, t);

    for (int i = t; i < 4096; i += 256) {
        int o = i >> 6, c = i & 63;
        Wt[c * 68 + o] = W[i];
    }
    int tile0 = blockIdx.x * 64;
    for (int i = t; i < 1024; i += 256) {
        int f = i * 4;
        int pl = f >> 6, c = f & 63;
        int pt = tile0 + pl; pt = (pt < N) ? pt : N - 1;
        *(float4*)&xs[f] = *(const float4*)&x[(size_t)pt * 64 + c];
    }
    __syncthreads();

    int og = t & 15, pg = t >> 4;
    int o0 = og * 4;
    float4 bias = *(const float4*)&b[o0];

    u64 acc2[4][2];
    #pragma unroll
    for (int a = 0; a < 4; a++) { acc2[a][0] = 0ULL; acc2[a][1] = 0ULL; }

    #pragma unroll
    for (int c4 = 0; c4 < 16; c4++) {
        u64 wlo[4], whi[4];
        #pragma unroll
        for (int k = 0; k < 4; k++) {
            const float* wr = &Wt[(4 * c4 + k) * 68 + o0];
            wlo[k] = *(const u64*)wr;
            whi[k] = *(const u64*)(wr + 2);
        }
        #pragma unroll
        for (int pp = 0; pp < 4; pp++) {
            float4 x4 = *(const float4*)&xs[(pg * 4 + pp) * 64 + 4 * c4];
            u64 xb0 = pk2(x4.x, x4.x), xb1 = pk2(x4.y, x4.y);
            u64 xb2 = pk2(x4.z, x4.z), xb3 = pk2(x4.w, x4.w);
            acc2[pp][0] = fma2(wlo[0], xb0, acc2[pp][0]);
            acc2[pp][1] = fma2(whi[0], xb0, acc2[pp][1]);
            acc2[pp][0] = fma2(wlo[1], xb1, acc2[pp][0]);
            acc2[pp][1] = fma2(whi[1], xb1, acc2[pp][1]);
            acc2[pp][0] = fma2(wlo[2], xb2, acc2[pp][0]);
            acc2[pp][1] = fma2(whi[2], xb2, acc2[pp][1]);
            acc2[pp][0] = fma2(wlo[3], xb3, acc2[pp][0]);
            acc2[pp][1] = fma2(whi[3], xb3, acc2[pp][1]);
        }
    }
    #pragma unroll
    for (int pp = 0; pp < 4; pp++) {
        int pt = tile0 + pg * 4 + pp;
        if (pt < N) {
            float2 lo = upk2(acc2[pp][0]), hi = upk2(acc2[pp][1]);
            __half2 h0 = __floats2half2_rn(lo.x + bias.x, lo.y + bias.y);
            __half2 h1 = __floats2half2_rn(hi.x + bias.z, hi.y + bias.w);
            uint2 st;
            st.x = *(unsigned int*)&h0;
            st.y = *(unsigned int*)&h1;
            *(uint2*)(dst + (size_t)pt * 32 + og * 2) = st;
        }
    }
}

// ---------------------------------------------------------------------------
// Kernel B: fused attention, f32x2 packed math. Block = 8 points, 128 thr.
// ---------------------------------------------------------------------------
__global__ __launch_bounds__(128, 8) void attn2(
    const float* __restrict__ p, const int* __restrict__ idx,
    float* __restrict__ out, int N)
{
    __shared__ __align__(16) uint2  vbuf[8][16][16];   // fp16 v, swizzled
    __shared__ __align__(16) float  wex[8][16][12];
    __shared__ __align__(16) float  Hs[8][3][8];
    __shared__ float hs[8][16][4];
    __shared__ int   idxs[8][16];
    __shared__ float pns[8][4];

    int t = threadIdx.x, lane = t & 31, wid = t >> 5;
    int n0 = blockIdx.x * 8;

    int lpA = t >> 4, sub = t & 15;
    int nA  = n0 + lpA;
    int nAc = (nA < N) ? nA : N - 1;

    // prologue: indices, center coords, h-MLP
    int id0 = idx[(size_t)nAc * 16 + sub];
    id0 = (id0 < 0) ? 0 : ((id0 >= N) ? N - 1 : id0);
    idxs[lpA][sub] = id0;
    if (lane < 6) {
        int pp = wid * 2 + lane / 3, d = lane % 3;
        int np = n0 + pp; np = (np < N) ? np : N - 1;
        pns[pp][d] = p[(size_t)np * 3 + d];
    }
    __syncwarp();
    {
        float prx = p[(size_t)id0 * 3 + 0] - pns[lpA][0];
        float pry = p[(size_t)id0 * 3 + 1] - pns[lpA][1];
        float prz = p[(size_t)id0 * 3 + 2] - pns[lpA][2];
        hs[lpA][sub][0] = fmaxf(fmaf(prx, c_P.fw1[0], fmaf(pry, c_P.fw1[1], fmaf(prz, c_P.fw1[2], c_P.fb1[0]))), 0.f);
        hs[lpA][sub][1] = fmaxf(fmaf(prx, c_P.fw1[3], fmaf(pry, c_P.fw1[4], fmaf(prz, c_P.fw1[5], c_P.fb1[1]))), 0.f);
        hs[lpA][sub][2] = fmaxf(fmaf(prx, c_P.fw1[6], fmaf(pry, c_P.fw1[7], fmaf(prz, c_P.fw1[8], c_P.fb1[2]))), 0.f);
    }
    float4 Ac = c_P.A[sub];
    float4 T0 = c_P.T0[sub], T1 = c_P.T1[sub], T2 = c_P.T2[sub];
    float4 TBc = c_P.TB[sub];
    float4 xq4 = ldg_h4(g_xq, (size_t)nAc, sub);
    // packed per-channel constants (xy / zw pairs)
    u64 A_xy  = pk2(Ac.x, Ac.y),  A_zw  = pk2(Ac.z, Ac.w);
    u64 T0_xy = pk2(T0.x, T0.y),  T0_zw = pk2(T0.z, T0.w);
    u64 T1_xy = pk2(T1.x, T1.y),  T1_zw = pk2(T1.z, T1.w);
    u64 T2_xy = pk2(T2.x, T2.y),  T2_zw = pk2(T2.z, T2.w);
    u64 TB_xy = pk2(TBc.x - Ac.x * xq4.x, TBc.y - Ac.y * xq4.y);
    u64 TB_zw = pk2(TBc.z - Ac.z * xq4.z, TBc.w - Ac.w * xq4.w);
    __syncwarp();

    // ---- Phase A: v = relu(A*xk + T.h + TBm) -> swizzled fp16 vbuf ---------
    const __half2 hzero2 = __float2half2_rn(0.f);
    #pragma unroll
    for (int j = 0; j < 16; j++) {
        int id = idxs[lpA][j];
        u64 hb0 = pk2(hs[lpA][j][0], hs[lpA][j][0]);
        u64 hb1 = pk2(hs[lpA][j][1], hs[lpA][j][1]);
        u64 hb2 = pk2(hs[lpA][j][2], hs[lpA][j][2]);
        uint2 u = *(const uint2*)(g_xk + (size_t)id * 32 + sub * 2);
        float2 fa = __half22float2(*(__half2*)&u.x);
        float2 fb = __half22float2(*(__half2*)&u.y);
        u64 xk_xy = pk2(fa.x, fa.y), xk_zw = pk2(fb.x, fb.y);
        u64 v_xy = fma2(A_xy, xk_xy, fma2(T2_xy, hb2, fma2(T1_xy, hb1, fma2(T0_xy, hb0, TB_xy))));
        u64 v_zw = fma2(A_zw, xk_zw, fma2(T2_zw, hb2, fma2(T1_zw, hb1, fma2(T0_zw, hb0, TB_zw))));
        float2 vxy = upk2(v_xy), vzw = upk2(v_zw);
        __half2 ha = __hmax2(__floats2half2_rn(vxy.x, vxy.y), hzero2);
        __half2 hb = __hmax2(__floats2half2_rn(vzw.x, vzw.y), hzero2);
        uint2 st;
        st.x = *(unsigned int*)&ha;
        st.y = *(unsigned int*)&hb;
        vbuf[lpA][j][(sub + j) & 15] = st;
    }
    __syncwarp();

    // ---- Phase B: 64->8 projection (f32x2) + BN2 + w2 + softmax ------------
    int lpB = wid * 2 + (lane >> 4), jj = lane & 15;
    {
        u64 acc2[4];
        #pragma unroll
        for (int o = 0; o < 4; o++) acc2[o] = 0ULL;
        #pragma unroll
        for (int g = 0; g < 16; g++) {
            uint2 u = vbuf[lpB][jj][(g + jj) & 15];
            float2 fa = __half22float2(*(__half2*)&u.x);
            float2 fb = __half22float2(*(__half2*)&u.y);
            u64 b0 = pk2(fa.x, fa.x), b1 = pk2(fa.y, fa.y);
            u64 b2 = pk2(fb.x, fb.x), b3 = pk2(fb.y, fb.y);
            const u64* wp = (const u64*)&c_P.w1p[g * 16];
            #pragma unroll
            for (int op = 0; op < 4; op++) {
                acc2[op] = fma2(wp[0 * 4 + op], b0, acc2[op]);
                acc2[op] = fma2(wp[1 * 4 + op], b1, acc2[op]);
                acc2[op] = fma2(wp[2 * 4 + op], b2, acc2[op]);
                acc2[op] = fma2(wp[3 * 4 + op], b3, acc2[op]);
            }
        }
        float acc[8], y[8];
        #pragma unroll
        for (int op = 0; op < 4; op++) {
            float2 f = upk2(acc2[op]);
            acc[2 * op] = f.x; acc[2 * op + 1] = f.y;
        }
        #pragma unroll
        for (int o = 0; o < 8; o++)
            y[o] = fmaxf(fmaf(c_P.a2[o], acc[o], c_P.c2f[o]), 0.f);
        #pragma unroll
        for (int u = 0; u < 8; u++) {
            float s = c_P.wb2[u];
            #pragma unroll
            for (int o = 0; o < 8; o++) s = fmaf(y[o], c_P.w2[u * 8 + o], s);
            acc[u] = s;                       // reuse acc as z
        }
        #pragma unroll
        for (int u = 0; u < 8; u++) {
            float z = acc[u];
            float m = z;
            m = fmaxf(m, __shfl_xor_sync(0xffffffffu, m, 1));
            m = fmaxf(m, __shfl_xor_sync(0xffffffffu, m, 2));
            m = fmaxf(m, __shfl_xor_sync(0xffffffffu, m, 4));
            m = fmaxf(m, __shfl_xor_sync(0xffffffffu, m, 8));
            float ev = __expf(z - m);
            float s = ev;
            s += __shfl_xor_sync(0xffffffffu, s, 1);
            s += __shfl_xor_sync(0xffffffffu, s, 2);
            s += __shfl_xor_sync(0xffffffffu, s, 4);
            s += __shfl_xor_sync(0xffffffffu, s, 8);
            wex[lpB][jj][u] = ev * __frcp_rn(s);
        }
    }
    __syncwarp();

    // ---- H[u] = sum_j h_j * wex_j[u]  (per point, 3x8 values) --------------
    if (sub < 8) {
        float H0 = 0.f, H1 = 0.f, H2 = 0.f;
        #pragma unroll
        for (int j = 0; j < 16; j++) {
            float w = wex[lpA][j][sub];
            H0 = fmaf(hs[lpA][j][0], w, H0);
            H1 = fmaf(hs[lpA][j][1], w, H1);
            H2 = fmaf(hs[lpA][j][2], w, H2);
        }
        Hs[lpA][0][sub] = H0;
        Hs[lpA][1][sub] = H1;
        Hs[lpA][2][sub] = H2;
    }
    __syncwarp();

    // ---- Phase 2: out_c = pw2_c.H[u] + pb2_c + sum_j xv_jc * wex_j[u] ------
    float4 q0 = c_P.R0[sub], q1 = c_P.R1[sub], q2 = c_P.R2[sub], qb = c_P.RB[sub];
    int u0 = (sub & 1) * 4;
    float4 H0v = *(const float4*)&Hs[lpA][0][u0];
    float4 H1v = *(const float4*)&Hs[lpA][1][u0];
    float4 H2v = *(const float4*)&Hs[lpA][2][u0];
    float bx = fmaf(q0.x, H0v.x, fmaf(q1.x, H1v.x, fmaf(q2.x, H2v.x, qb.x)));
    float by = fmaf(q0.y, H0v.y, fmaf(q1.y, H1v.y, fmaf(q2.y, H2v.y, qb.y)));
    float bz = fmaf(q0.z, H0v.z, fmaf(q1.z, H1v.z, fmaf(q2.z, H2v.z, qb.z)));
    float bw = fmaf(q0.w, H0v.w, fmaf(q1.w, H1v.w, fmaf(q2.w, H2v.w, qb.w)));

    u64 oxy = 0ULL, ozw = 0ULL;
    #pragma unroll
    for (int j = 0; j < 16; j++) {
        int id = idxs[lpA][j];
        uint2 u = *(const uint2*)(g_xv + (size_t)id * 32 + sub * 2);
        float2 fa = __half22float2(*(__half2*)&u.x);
        float2 fb = __half22float2(*(__half2*)&u.y);
        u64 wn_xy = *(const u64*)&wex[lpA][j][u0];
        u64 wn_zw = *(const u64*)&wex[lpA][j][u0 + 2];
        oxy = fma2(pk2(fa.x, fa.y), wn_xy, oxy);
        ozw = fma2(pk2(fb.x, fb.y), wn_zw, ozw);
    }
    if (nA < N) {
        float2 lo = upk2(oxy), hi = upk2(ozw);
        *(float4*)&out[(size_t)nA * 64 + sub * 4] =
            make_float4(lo.x + bx, lo.y + by, hi.x + bz, hi.y + bw);
    }
}

// ---------------------------------------------------------------------------
extern "C" void kernel_launch(void* const* d_in, const int* in_sizes, int n_in,
                              void* d_out, int out_size)
{
    const float* p   = (const float*)d_in[0];
    const float* x   = (const float*)d_in[1];
    const int* idx   = (const int*)d_in[2];
    const float* Wq  = (const float*)d_in[3];
    const float* bq  = (const float*)d_in[4];
    const float* Wk  = (const float*)d_in[5];
    const float* bk  = (const float*)d_in[6];
    const float* Wv  = (const float*)d_in[7];
    const float* bv  = (const float*)d_in[8];

    PrepArgs pa;
    pa.pw1  = (const float*)d_in[9];
    pa.pb1  = (const float*)d_in[10];
    pa.pbng = (const float*)d_in[11];
    pa.pbnb = (const float*)d_in[12];
    pa.pbnm = (const float*)d_in[13];
    pa.pbnv = (const float*)d_in[14];
    pa.pw2  = (const float*)d_in[15];
    pa.pb2  = (const float*)d_in[16];
    pa.bn1g = (const float*)d_in[17];
    pa.bn1b = (const float*)d_in[18];
    pa.bn1m = (const float*)d_in[19];
    pa.bn1v = (const float*)d_in[20];
    pa.w1   = (const float*)d_in[21];
    pa.wb1  = (const float*)d_in[22];
    pa.bn2g = (const float*)d_in[23];
    pa.bn2b = (const float*)d_in[24];
    pa.bn2m = (const float*)d_in[25];
    pa.bn2v = (const float*)d_in[26];
    pa.w2   = (const float*)d_in[27];
    pa.wb2  = (const float*)d_in[28];

    int N = in_sizes[1] / 64;

    dim3 pgrid((N + 63) / 64, 3);
    proj2<<<pgrid, 256>>>(x, Wq, bq, Wk, bk, Wv, bv, pa, N);

    void* sp = nullptr;
    cudaGetSymbolAddress(&sp, g_stage);
    cudaMemcpyToSymbolAsync(c_P, sp, sizeof(CParams), 0,
                            cudaMemcpyDeviceToDevice, 0);

    attn2<<<(N + 7) / 8, 128>>>(p, idx, (float*)d_out, N);
}

// round 14
// speedup vs baseline: 1.3519x; 1.0283x over previous
#include <cuda_runtime.h>
#include <cuda_fp16.h>

#define NMAX 100000
#define EPSF 1e-5f

typedef unsigned long long u64;
typedef unsigned int u32;

__device__ __forceinline__ u64 pk2(float lo, float hi) {
    u64 r; asm("mov.b64 %0, {%1,%2};" : "=l"(r) : "f"(lo), "f"(hi)); return r;
}
__device__ __forceinline__ float2 upk2(u64 v) {
    float2 r; asm("mov.b64 {%0,%1}, %2;" : "=f"(r.x), "=f"(r.y) : "l"(v)); return r;
}
__device__ __forceinline__ u64 fma2(u64 a, u64 b, u64 c) {
    u64 d; asm("fma.rn.f32x2 %0, %1, %2, %3;" : "=l"(d) : "l"(a), "l"(b), "l"(c)); return d;
}
__device__ __forceinline__ u32 smem_u32(const void* p) {
    return (u32)__cvta_generic_to_shared(p);
}
__device__ __forceinline__ u32 h2u(float a, float b) {
    __half2 h = __floats2half2_rn(a, b);
    return *(u32*)&h;
}

// q/k/v projection scratch in fp16 (device globals: allocation-free).
__device__ __half2 g_xq[NMAX * 32];
__device__ __half2 g_xk[NMAX * 32];
__device__ __half2 g_xv[NMAX * 32];

// mma weight fragment tables (fp16), coalesced global reads in attn2.
__device__ u32 g_w1b0[4][32];   // B frag (b0) of w1 for k-step ks, per lane
__device__ u32 g_w1b1[4][32];   // B frag (b1)
__device__ u32 g_w2b[32];       // B frag of w2 (m16n8k8), per lane

__device__ __forceinline__ float4 ldg_h4(const __half2* __restrict__ base,
                                         size_t row, int sub) {
    uint2 u = *(const uint2*)(base + row * 32 + sub * 2);
    __half2 a = *(__half2*)&u.x, b = *(__half2*)&u.y;
    float2 fa = __half22float2(a), fb = __half22float2(b);
    return make_float4(fa.x, fa.y, fb.x, fb.y);
}

// ---------------------------------------------------------------------------
// Folded constants, staged on device (by proj2 block (0,0)) then copied into
// __constant__ via stream-ordered memcpyToSymbolAsync.
// ---------------------------------------------------------------------------
struct CParams {
    float4 A[16];                           // bn1 scale folded
    float4 T0[16], T1[16], T2[16], TB[16];  // A*pw2 cols, A*pb2 + b1
    float4 R0[16], R1[16], R2[16], RB[16];  // raw pw2 cols, raw pb2
    float a2[8], c2f[8];                    // y = relu(a2*acc + c2f)
    float wb2[8];
    float fw1[9], fb1[3];                   // folded p-MLP layer1
    float pad[4];
};
__device__ CParams g_stage;
__constant__ CParams c_P;

struct PrepArgs {
    const float *pw1, *pb1, *pbng, *pbnb, *pbnm, *pbnv, *pw2, *pb2;
    const float *bn1g, *bn1b, *bn1m, *bn1v, *w1, *wb1;
    const float *bn2g, *bn2b, *bn2m, *bn2v, *w2, *wb2;
};

__device__ __forceinline__ void do_prep(const PrepArgs& a, int t) {
    // t in [0, 256)
    if (t < 64) {
        float g  = a.bn1g[t] * rsqrtf(a.bn1v[t] + EPSF);
        float b1 = a.bn1b[t] - a.bn1m[t] * g;
        float r0 = a.pw2[t * 3 + 0], r1 = a.pw2[t * 3 + 1], r2 = a.pw2[t * 3 + 2];
        float rb = a.pb2[t];
        ((float*)g_stage.A )[t] = g;
        ((float*)g_stage.T0)[t] = g * r0;
        ((float*)g_stage.T1)[t] = g * r1;
        ((float*)g_stage.T2)[t] = g * r2;
        ((float*)g_stage.TB)[t] = g * rb + b1;
        ((float*)g_stage.R0)[t] = r0;
        ((float*)g_stage.R1)[t] = r1;
        ((float*)g_stage.R2)[t] = r2;
        ((float*)g_stage.RB)[t] = rb;
    }
    // w1 fragment tables: B[ch][o] = w1[o][ch]; m16n8k16 B frag:
    //   b0(lane) = {B[k0][n], B[k0+1][n]},  b1 = same k0+8;  n=l/4, k0=16ks+2(l%4)
    if (t < 128) {
        int ks = t >> 5, l = t & 31;
        int n = l >> 2, k0 = ks * 16 + 2 * (l & 3);
        g_w1b0[ks][l] = h2u(a.w1[n * 64 + k0],     a.w1[n * 64 + k0 + 1]);
        g_w1b1[ks][l] = h2u(a.w1[n * 64 + k0 + 8], a.w1[n * 64 + k0 + 9]);
    }
    // w2 fragment (m16n8k8): B[o][u'] = w2[u'][o];  b(lane) = {B[k0][n], B[k0+1][n]}
    if (t < 32) {
        int n = t >> 2, k0 = 2 * (t & 3);
        g_w2b[t] = h2u(a.w2[n * 8 + k0], a.w2[n * 8 + k0 + 1]);
    }
    if (t < 8) {
        float a2 = a.bn2g[t] * rsqrtf(a.bn2v[t] + EPSF);
        g_stage.a2[t]  = a2;
        g_stage.c2f[t] = a2 * a.wb1[t] + (a.bn2b[t] - a.bn2m[t] * a2);
        g_stage.wb2[t] = a.wb2[t];
    }
    if (t < 3) {
        float pa = a.pbng[t] * rsqrtf(a.pbnv[t] + EPSF);
        g_stage.fw1[t * 3 + 0] = pa * a.pw1[t * 3 + 0];
        g_stage.fw1[t * 3 + 1] = pa * a.pw1[t * 3 + 1];
        g_stage.fw1[t * 3 + 2] = pa * a.pw1[t * 3 + 2];
        g_stage.fb1[t] = pa * a.pb1[t] + (a.pbnb[t] - a.pbnm[t] * pa);
    }
}

// ---------------------------------------------------------------------------
// Kernel A: q/k/v projection, fp16 output, f32x2 packed math.
// ---------------------------------------------------------------------------
__global__ __launch_bounds__(256) void proj2(
    const float* __restrict__ x,
    const float* __restrict__ Wq, const float* __restrict__ bq,
    const float* __restrict__ Wk, const float* __restrict__ bk,
    const float* __restrict__ Wv, const float* __restrict__ bv,
    PrepArgs pa, int N)
{
    const float* W; const float* b; __half2* dst;
    if (blockIdx.y == 0)      { W = Wq; b = bq; dst = g_xq; }
    else if (blockIdx.y == 1) { W = Wk; b = bk; dst = g_xk; }
    else                      { W = Wv; b = bv; dst = g_xv; }

    __shared__ __align__(16) float Wt[64 * 68];
    __shared__ __align__(16) float xs[64 * 64];
    int t = threadIdx.x;

    if (blockIdx.x == 0 && blockIdx.y == 0)
        do_prep(pa, t);

    for (int i = t; i < 4096; i += 256) {
        int o = i >> 6, c = i & 63;
        Wt[c * 68 + o] = W[i];
    }
    int tile0 = blockIdx.x * 64;
    for (int i = t; i < 1024; i += 256) {
        int f = i * 4;
        int pl = f >> 6, c = f & 63;
        int pt = tile0 + pl; pt = (pt < N) ? pt : N - 1;
        *(float4*)&xs[f] = *(const float4*)&x[(size_t)pt * 64 + c];
    }
    __syncthreads();

    int og = t & 15, pg = t >> 4;
    int o0 = og * 4;
    float4 bias = *(const float4*)&b[o0];

    u64 acc2[4][2];
    #pragma unroll
    for (int a = 0; a < 4; a++) { acc2[a][0] = 0ULL; acc2[a][1] = 0ULL; }

    #pragma unroll
    for (int c4 = 0; c4 < 16; c4++) {
        u64 wlo[4], whi[4];
        #pragma unroll
        for (int k = 0; k < 4; k++) {
            const float* wr = &Wt[(4 * c4 + k) * 68 + o0];
            wlo[k] = *(const u64*)wr;
            whi[k] = *(const u64*)(wr + 2);
        }
        #pragma unroll
        for (int pp = 0; pp < 4; pp++) {
            float4 x4 = *(const float4*)&xs[(pg * 4 + pp) * 64 + 4 * c4];
            u64 xb0 = pk2(x4.x, x4.x), xb1 = pk2(x4.y, x4.y);
            u64 xb2 = pk2(x4.z, x4.z), xb3 = pk2(x4.w, x4.w);
            acc2[pp][0] = fma2(wlo[0], xb0, acc2[pp][0]);
            acc2[pp][1] = fma2(whi[0], xb0, acc2[pp][1]);
            acc2[pp][0] = fma2(wlo[1], xb1, acc2[pp][0]);
            acc2[pp][1] = fma2(whi[1], xb1, acc2[pp][1]);
            acc2[pp][0] = fma2(wlo[2], xb2, acc2[pp][0]);
            acc2[pp][1] = fma2(whi[2], xb2, acc2[pp][1]);
            acc2[pp][0] = fma2(wlo[3], xb3, acc2[pp][0]);
            acc2[pp][1] = fma2(whi[3], xb3, acc2[pp][1]);
        }
    }
    #pragma unroll
    for (int pp = 0; pp < 4; pp++) {
        int pt = tile0 + pg * 4 + pp;
        if (pt < N) {
            float2 lo = upk2(acc2[pp][0]), hi = upk2(acc2[pp][1]);
            __half2 h0 = __floats2half2_rn(lo.x + bias.x, lo.y + bias.y);
            __half2 h1 = __floats2half2_rn(hi.x + bias.z, hi.y + bias.w);
            uint2 st;
            st.x = *(u32*)&h0;
            st.y = *(u32*)&h1;
            *(uint2*)(dst + (size_t)pt * 32 + og * 2) = st;
        }
    }
}

// ---------------------------------------------------------------------------
// Kernel B: fused attention. Block = 8 points, 128 threads, warp-local.
// Phase B = tensor-core path: per point, z[16x8] = v[16x64] @ w1^T via
// 4x mma.m16n8k16 (ldmatrix from swizzled fp16 vbuf), BN2+relu in-fragment,
// zz = y @ w2^T via 1x mma.m16n8k8 (wb2 in initial accumulator), softmax over
// the j-column via shfl_xor(4,8,16).
// ---------------------------------------------------------------------------
__global__ __launch_bounds__(128, 8) void attn2(
    const float* __restrict__ p, const int* __restrict__ idx,
    float* __restrict__ out, int N)
{
    __shared__ __align__(128) char  vbufc[8 * 2048];   // [pt][16 rows][128B], XOR-16B swz
    __shared__ __align__(16) float  wex[8][16][12];
    __shared__ __align__(16) float  Hs[8][3][8];
    __shared__ float hs[8][16][4];
    __shared__ int   idxs[8][16];
    __shared__ float pns[8][4];

    int t = threadIdx.x, lane = t & 31, wid = t >> 5;
    int n0 = blockIdx.x * 8;

    int lpA = t >> 4, sub = t & 15;
    int nA  = n0 + lpA;
    int nAc = (nA < N) ? nA : N - 1;

    // prologue: indices, center coords, h-MLP
    int id0 = idx[(size_t)nAc * 16 + sub];
    id0 = (id0 < 0) ? 0 : ((id0 >= N) ? N - 1 : id0);
    idxs[lpA][sub] = id0;
    if (lane < 6) {
        int pp = wid * 2 + lane / 3, d = lane % 3;
        int np = n0 + pp; np = (np < N) ? np : N - 1;
        pns[pp][d] = p[(size_t)np * 3 + d];
    }
    __syncwarp();
    {
        float prx = p[(size_t)id0 * 3 + 0] - pns[lpA][0];
        float pry = p[(size_t)id0 * 3 + 1] - pns[lpA][1];
        float prz = p[(size_t)id0 * 3 + 2] - pns[lpA][2];
        hs[lpA][sub][0] = fmaxf(fmaf(prx, c_P.fw1[0], fmaf(pry, c_P.fw1[1], fmaf(prz, c_P.fw1[2], c_P.fb1[0]))), 0.f);
        hs[lpA][sub][1] = fmaxf(fmaf(prx, c_P.fw1[3], fmaf(pry, c_P.fw1[4], fmaf(prz, c_P.fw1[5], c_P.fb1[1]))), 0.f);
        hs[lpA][sub][2] = fmaxf(fmaf(prx, c_P.fw1[6], fmaf(pry, c_P.fw1[7], fmaf(prz, c_P.fw1[8], c_P.fb1[2]))), 0.f);
    }
    float4 Ac = c_P.A[sub];
    float4 T0 = c_P.T0[sub], T1 = c_P.T1[sub], T2 = c_P.T2[sub];
    float4 TBc = c_P.TB[sub];
    float4 xq4 = ldg_h4(g_xq, (size_t)nAc, sub);
    u64 A_xy  = pk2(Ac.x, Ac.y),  A_zw  = pk2(Ac.z, Ac.w);
    u64 T0_xy = pk2(T0.x, T0.y),  T0_zw = pk2(T0.z, T0.w);
    u64 T1_xy = pk2(T1.x, T1.y),  T1_zw = pk2(T1.z, T1.w);
    u64 T2_xy = pk2(T2.x, T2.y),  T2_zw = pk2(T2.z, T2.w);
    u64 TB_xy = pk2(TBc.x - Ac.x * xq4.x, TBc.y - Ac.y * xq4.y);
    u64 TB_zw = pk2(TBc.z - Ac.z * xq4.z, TBc.w - Ac.w * xq4.w);
    __syncwarp();

    // ---- Phase A: v = relu(A*xk + T.h + TBm) -> fp16 vbuf rows -------------
    const __half2 hzero2 = __float2half2_rn(0.f);
    {
        char* vrow0 = vbufc + lpA * 2048 + ((sub & 1) << 3);
        int cn = sub >> 1;   // nominal 16B chunk
        #pragma unroll
        for (int j = 0; j < 16; j++) {
            int id = idxs[lpA][j];
            u64 hb0 = pk2(hs[lpA][j][0], hs[lpA][j][0]);
            u64 hb1 = pk2(hs[lpA][j][1], hs[lpA][j][1]);
            u64 hb2 = pk2(hs[lpA][j][2], hs[lpA][j][2]);
            uint2 u = *(const uint2*)(g_xk + (size_t)id * 32 + sub * 2);
            float2 fa = __half22float2(*(__half2*)&u.x);
            float2 fb = __half22float2(*(__half2*)&u.y);
            u64 v_xy = fma2(A_xy, pk2(fa.x, fa.y), fma2(T2_xy, hb2, fma2(T1_xy, hb1, fma2(T0_xy, hb0, TB_xy))));
            u64 v_zw = fma2(A_zw, pk2(fb.x, fb.y), fma2(T2_zw, hb2, fma2(T1_zw, hb1, fma2(T0_zw, hb0, TB_zw))));
            float2 vxy = upk2(v_xy), vzw = upk2(v_zw);
            __half2 ha = __hmax2(__floats2half2_rn(vxy.x, vxy.y), hzero2);
            __half2 hb = __hmax2(__floats2half2_rn(vzw.x, vzw.y), hzero2);
            uint2 st;
            st.x = *(u32*)&ha;
            st.y = *(u32*)&hb;
            *(uint2*)(vrow0 + j * 128 + ((cn ^ (j & 7)) << 4)) = st;
        }
    }
    __syncwarp();

    // ---- Phase B: tensor-core MLP + softmax --------------------------------
    {
        u32 b0f[4], b1f[4];
        #pragma unroll
        for (int ks = 0; ks < 4; ks++) { b0f[ks] = g_w1b0[ks][lane]; b1f[ks] = g_w1b1[ks][lane]; }
        u32 w2f = g_w2b[lane];
        int uo = 2 * (lane & 3);
        float a2lo = c_P.a2[uo],  a2hi = c_P.a2[uo + 1];
        float c2lo = c_P.c2f[uo], c2hi = c_P.c2f[uo + 1];
        float wblo = c_P.wb2[uo], wbhi = c_P.wb2[uo + 1];

        int tt = lane >> 3, r = lane & 7;
        int m = r + ((tt & 1) << 3);
        int jrow = lane >> 2;

        #pragma unroll
        for (int pt4 = 0; pt4 < 2; pt4++) {
            int lp = wid * 2 + pt4;
            u32 vbase = smem_u32(vbufc) + lp * 2048 + m * 128;
            float c0 = 0.f, c1 = 0.f, c2 = 0.f, c3 = 0.f;
            #pragma unroll
            for (int ks = 0; ks < 4; ks++) {
                int chunk = (((ks << 1) | (tt >> 1)) ^ (m & 7));
                u32 a0, a1, a2r, a3;
                asm volatile(
                    "ldmatrix.sync.aligned.m8n8.x4.shared.b16 {%0,%1,%2,%3}, [%4];"
                    : "=r"(a0), "=r"(a1), "=r"(a2r), "=r"(a3)
                    : "r"(vbase + (chunk << 4)));
                asm volatile(
                    "mma.sync.aligned.m16n8k16.row.col.f32.f16.f16.f32 "
                    "{%0,%1,%2,%3},{%4,%5,%6,%7},{%8,%9},{%0,%1,%2,%3};"
                    : "+f"(c0), "+f"(c1), "+f"(c2), "+f"(c3)
                    : "r"(a0), "r"(a1), "r"(a2r), "r"(a3), "r"(b0f[ks]), "r"(b1f[ks]));
            }
            // BN2 + relu in fragment, pack to A-frag of m16n8k8
            u32 ya = h2u(fmaxf(fmaf(a2lo, c0, c2lo), 0.f), fmaxf(fmaf(a2hi, c1, c2hi), 0.f));
            u32 yb = h2u(fmaxf(fmaf(a2lo, c2, c2lo), 0.f), fmaxf(fmaf(a2hi, c3, c2hi), 0.f));
            float d0 = wblo, d1 = wbhi, d2 = wblo, d3 = wbhi;
            asm volatile(
                "mma.sync.aligned.m16n8k8.row.col.f32.f16.f16.f32 "
                "{%0,%1,%2,%3},{%4,%5},{%6},{%0,%1,%2,%3};"
                : "+f"(d0), "+f"(d1), "+f"(d2), "+f"(d3)
                : "r"(ya), "r"(yb), "r"(w2f));
            // softmax over j (column uo: d0/d2, column uo+1: d1/d3)
            float m0 = fmaxf(d0, d2);
            m0 = fmaxf(m0, __shfl_xor_sync(0xffffffffu, m0, 4));
            m0 = fmaxf(m0, __shfl_xor_sync(0xffffffffu, m0, 8));
            m0 = fmaxf(m0, __shfl_xor_sync(0xffffffffu, m0, 16));
            float m1 = fmaxf(d1, d3);
            m1 = fmaxf(m1, __shfl_xor_sync(0xffffffffu, m1, 4));
            m1 = fmaxf(m1, __shfl_xor_sync(0xffffffffu, m1, 8));
            m1 = fmaxf(m1, __shfl_xor_sync(0xffffffffu, m1, 16));
            float e0 = __expf(d0 - m0), e2 = __expf(d2 - m0);
            float e1 = __expf(d1 - m1), e3 = __expf(d3 - m1);
            float s0 = e0 + e2, s1 = e1 + e3;
            s0 += __shfl_xor_sync(0xffffffffu, s0, 4);
            s0 += __shfl_xor_sync(0xffffffffu, s0, 8);
            s0 += __shfl_xor_sync(0xffffffffu, s0, 16);
            s1 += __shfl_xor_sync(0xffffffffu, s1, 4);
            s1 += __shfl_xor_sync(0xffffffffu, s1, 8);
            s1 += __shfl_xor_sync(0xffffffffu, s1, 16);
            float r0 = __frcp_rn(s0), r1 = __frcp_rn(s1);
            *(float2*)&wex[lp][jrow][uo]     = make_float2(e0 * r0, e1 * r1);
            *(float2*)&wex[lp][jrow + 8][uo] = make_float2(e2 * r0, e3 * r1);
        }
    }
    __syncwarp();

    // ---- H[u] = sum_j h_j * wex_j[u]  (per point, 3x8 values) --------------
    if (sub < 8) {
        float H0 = 0.f, H1 = 0.f, H2 = 0.f;
        #pragma unroll
        for (int j = 0; j < 16; j++) {
            float w = wex[lpA][j][sub];
            H0 = fmaf(hs[lpA][j][0], w, H0);
            H1 = fmaf(hs[lpA][j][1], w, H1);
            H2 = fmaf(hs[lpA][j][2], w, H2);
        }
        Hs[lpA][0][sub] = H0;
        Hs[lpA][1][sub] = H1;
        Hs[lpA][2][sub] = H2;
    }
    __syncwarp();

    // ---- Phase 2: out_c = pw2_c.H[u] + pb2_c + sum_j xv_jc * wex_j[u] ------
    float4 q0 = c_P.R0[sub], q1 = c_P.R1[sub], q2 = c_P.R2[sub], qb = c_P.RB[sub];
    int u0 = (sub & 1) * 4;
    float4 H0v = *(const float4*)&Hs[lpA][0][u0];
    float4 H1v = *(const float4*)&Hs[lpA][1][u0];
    float4 H2v = *(const float4*)&Hs[lpA][2][u0];
    float bx = fmaf(q0.x, H0v.x, fmaf(q1.x, H1v.x, fmaf(q2.x, H2v.x, qb.x)));
    float by = fmaf(q0.y, H0v.y, fmaf(q1.y, H1v.y, fmaf(q2.y, H2v.y, qb.y)));
    float bz = fmaf(q0.z, H0v.z, fmaf(q1.z, H1v.z, fmaf(q2.z, H2v.z, qb.z)));
    float bw = fmaf(q0.w, H0v.w, fmaf(q1.w, H1v.w, fmaf(q2.w, H2v.w, qb.w)));

    u64 oxy = 0ULL, ozw = 0ULL;
    #pragma unroll
    for (int j = 0; j < 16; j++) {
        int id = idxs[lpA][j];
        uint2 u = *(const uint2*)(g_xv + (size_t)id * 32 + sub * 2);
        float2 fa = __half22float2(*(__half2*)&u.x);
        float2 fb = __half22float2(*(__half2*)&u.y);
        u64 wn_xy = *(const u64*)&wex[lpA][j][u0];
        u64 wn_zw = *(const u64*)&wex[lpA][j][u0 + 2];
        oxy = fma2(pk2(fa.x, fa.y), wn_xy, oxy);
        ozw = fma2(pk2(fb.x, fb.y), wn_zw, ozw);
    }
    if (nA < N) {
        float2 lo = upk2(oxy), hi = upk2(ozw);
        *(float4*)&out[(size_t)nA * 64 + sub * 4] =
            make_float4(lo.x + bx, lo.y + by, hi.x + bz, hi.y + bw);
    }
}

// ---------------------------------------------------------------------------
extern "C" void kernel_launch(void* const* d_in, const int* in_sizes, int n_in,
                              void* d_out, int out_size)
{
    const float* p   = (const float*)d_in[0];
    const float* x   = (const float*)d_in[1];
    const int* idx   = (const int*)d_in[2];
    const float* Wq  = (const float*)d_in[3];
    const float* bq  = (const float*)d_in[4];
    const float* Wk  = (const float*)d_in[5];
    const float* bk  = (const float*)d_in[6];
    const float* Wv  = (const float*)d_in[7];
    const float* bv  = (const float*)d_in[8];

    PrepArgs pa;
    pa.pw1  = (const float*)d_in[9];
    pa.pb1  = (const float*)d_in[10];
    pa.pbng = (const float*)d_in[11];
    pa.pbnb = (const float*)d_in[12];
    pa.pbnm = (const float*)d_in[13];
    pa.pbnv = (const float*)d_in[14];
    pa.pw2  = (const float*)d_in[15];
    pa.pb2  = (const float*)d_in[16];
    pa.bn1g = (const float*)d_in[17];
    pa.bn1b = (const float*)d_in[18];
    pa.bn1m = (const float*)d_in[19];
    pa.bn1v = (const float*)d_in[20];
    pa.w1   = (const float*)d_in[21];
    pa.wb1  = (const float*)d_in[22];
    pa.bn2g = (const float*)d_in[23];
    pa.bn2b = (const float*)d_in[24];
    pa.bn2m = (const float*)d_in[25];
    pa.bn2v = (const float*)d_in[26];
    pa.w2   = (const float*)d_in[27];
    pa.wb2  = (const float*)d_in[28];

    int N = in_sizes[1] / 64;

    dim3 pgrid((N + 63) / 64, 3);
    proj2<<<pgrid, 256>>>(x, Wq, bq, Wk, bk, Wv, bv, pa, N);

    void* sp = nullptr;
    cudaGetSymbolAddress(&sp, g_stage);
    cudaMemcpyToSymbolAsync(c_P, sp, sizeof(CParams), 0,
                            cudaMemcpyDeviceToDevice, 0);

    attn2<<<(N + 7) / 8, 128>>>(p, idx, (float*)d_out, N);
}